// round 1
// baseline (speedup 1.0000x reference)
#include <cuda_runtime.h>

// ---------------------------------------------------------------------------
// ShapletLearner: B=2048 series (Q=1024), L=64 shapelets (K=32), S=993 windows
//   dist[b,s,l] = mean((win-shp)^2) = (wsq[s] - 2*dot)/K + ssq[l]
//   d[b,l] = min_s dist ; out[b,c] = sum_l d*fc_w[c,l] + fc_b[c]
// Strategy: 1 CTA per b. fp32 FMA-bound -> use packed fma.rn.f32x2 (FFMA2).
// ---------------------------------------------------------------------------

constexpr int Bc = 2048;
constexpr int Qc = 1024;
constexpr int Kc = 32;
constexpr int Lc = 64;
constexpr int Sc = Qc - Kc + 1;  // 993

// d += a*b (packed 2xf32)
#define FFMA2_ACC(d, a, b) \
    asm("fma.rn.f32x2 %0, %1, %2, %0;" : "+l"(d) : "l"(a), "l"(b))
// d = a*b + c (packed 2xf32)
#define FFMA2_3(d, a, b, c) \
    asm("fma.rn.f32x2 %0, %1, %2, %3;" : "=l"(d) : "l"(a), "l"(b), "l"(c))

static __device__ __forceinline__ unsigned long long pack_dup(float x) {
    unsigned long long r;
    asm("mov.b64 %0, {%1, %2};" : "=l"(r) : "f"(x), "f"(x));
    return r;
}
static __device__ __forceinline__ float lo_f(unsigned long long v) {
    return __uint_as_float((unsigned int)v);
}
static __device__ __forceinline__ float hi_f(unsigned long long v) {
    return __uint_as_float((unsigned int)(v >> 32));
}

__global__ __launch_bounds__(256) void shapelet_kernel(
    const float* __restrict__ ts,        // [B, Q]
    const float* __restrict__ shp,       // [L, K]
    const float* __restrict__ fc_w,      // [2, L]
    const float* __restrict__ fc_b,      // [2]
    float* __restrict__ out)             // [B, 2]
{
    __shared__ __align__(16) float ts_sh[Qc + 40];   // padded: reads reach s0+34
    __shared__ __align__(16) float shp_t[Kc * Lc];   // [k][l]
    __shared__ float ssq_sh[Lc];
    __shared__ float red[Lc * 33];                   // [l][sl], stride 33 (no conflicts)
    __shared__ float dsh[Lc];

    const int b   = blockIdx.x;
    const int tid = threadIdx.x;

    // ---- stage ts row (float4, coalesced) + zero pad ----
    {
        const float4* src = reinterpret_cast<const float4*>(ts + (size_t)b * Qc);
        reinterpret_cast<float4*>(ts_sh)[tid] = src[tid];
    }
    if (tid < 40) ts_sh[Qc + tid] = 0.0f;

    // ---- transpose shapelets into [k][l] ----
    #pragma unroll
    for (int idx = tid; idx < Lc * Kc; idx += 256) {
        int l = idx >> 5, k = idx & 31;
        shp_t[k * Lc + l] = shp[idx];
    }
    __syncthreads();

    // ---- ssq[l] = mean_k shp^2 ----
    if (tid < Lc) {
        float s = 0.0f;
        #pragma unroll
        for (int k = 0; k < Kc; k++) {
            float v = shp_t[k * Lc + tid];
            s = fmaf(v, v, s);
        }
        ssq_sh[tid] = s * (1.0f / Kc);
    }

    // ---- main: thread handles l = lg*8..lg*8+7, s = {(it*32+sl)*4 + i} ----
    const int lg = tid & 7;   // 8 l-groups
    const int sl = tid >> 3;  // 32 s-lanes

    float m[8];
    #pragma unroll
    for (int j = 0; j < 8; j++) m[j] = 3.4e38f;

    const ulonglong2* sp =
        reinterpret_cast<const ulonglong2*>(shp_t) + lg * 2;  // pair base for this l-group
    const unsigned long long neg2 = pack_dup(-2.0f);

    for (int it = 0; it < 8; it++) {
        const int s0 = (it * 32 + sl) * 4;
        if (s0 >= Sc) continue;

        unsigned long long acc[4][4];
        #pragma unroll
        for (int i = 0; i < 4; i++)
            #pragma unroll
            for (int p = 0; p < 4; p++) acc[i][p] = 0ull;

        // sliding duplicated-window registers
        unsigned long long wd[4];
        #pragma unroll
        for (int i = 0; i < 4; i++) wd[i] = pack_dup(ts_sh[s0 + i]);

        float wsq0 = 0.0f;

        #pragma unroll
        for (int k = 0; k < Kc; k++) {
            const ulonglong2 sa = sp[k * 16];       // shp pairs l..l+3
            const ulonglong2 sb = sp[k * 16 + 1];   // shp pairs l+4..l+7
            const float w0c = lo_f(wd[0]);
            wsq0 = fmaf(w0c, w0c, wsq0);
            #pragma unroll
            for (int i = 0; i < 4; i++) {
                FFMA2_ACC(acc[i][0], sa.x, wd[i]);
                FFMA2_ACC(acc[i][1], sa.y, wd[i]);
                FFMA2_ACC(acc[i][2], sb.x, wd[i]);
                FFMA2_ACC(acc[i][3], sb.y, wd[i]);
            }
            wd[0] = wd[1]; wd[1] = wd[2]; wd[2] = wd[3];
            if (k < Kc - 1) wd[3] = pack_dup(ts_sh[s0 + k + 4]);
        }

        // incremental window sum-of-squares for s0+1..s0+3
        const float t0 = ts_sh[s0],      t1 = ts_sh[s0 + 1],  t2 = ts_sh[s0 + 2];
        const float u0 = ts_sh[s0 + 32], u1 = ts_sh[s0 + 33], u2 = ts_sh[s0 + 34];
        float wsq[4];
        wsq[0] = wsq0;
        wsq[1] = wsq[0] - t0 * t0 + u0 * u0;
        wsq[2] = wsq[1] - t1 * t1 + u1 * u1;
        wsq[3] = wsq[2] - t2 * t2 + u2 * u2;

        const bool fullv = (s0 + 4 <= Sc);
        #pragma unroll
        for (int i = 0; i < 4; i++) {
            if (fullv || (s0 + i) < Sc) {
                const unsigned long long wq = pack_dup(wsq[i]);
                #pragma unroll
                for (int p = 0; p < 4; p++) {
                    unsigned long long v;
                    FFMA2_3(v, acc[i][p], neg2, wq);   // wsq - 2*dot (packed)
                    m[2 * p]     = fminf(m[2 * p],     lo_f(v));
                    m[2 * p + 1] = fminf(m[2 * p + 1], hi_f(v));
                }
            }
        }
    }

    // ---- cross-s_lane min reduction ----
    #pragma unroll
    for (int j = 0; j < 8; j++)
        red[(lg * 8 + j) * 33 + sl] = m[j];
    __syncthreads();

    if (tid < Lc) {
        float mm = red[tid * 33];
        #pragma unroll
        for (int r = 1; r < 32; r++) mm = fminf(mm, red[tid * 33 + r]);
        dsh[tid] = mm * (1.0f / Kc) + ssq_sh[tid];
    }
    __syncthreads();

    // ---- FC epilogue: warp 0 -> class 0, warp 1 -> class 1 ----
    if (tid < 2 * 32) {
        const int c    = tid >> 5;
        const int lane = tid & 31;
        float p = dsh[lane] * fc_w[c * Lc + lane]
                + dsh[lane + 32] * fc_w[c * Lc + lane + 32];
        #pragma unroll
        for (int off = 16; off > 0; off >>= 1)
            p += __shfl_down_sync(0xffffffffu, p, off);
        if (lane == 0) out[b * 2 + c] = p + fc_b[c];
    }
}

extern "C" void kernel_launch(void* const* d_in, const int* in_sizes, int n_in,
                              void* d_out, int out_size)
{
    (void)in_sizes; (void)n_in; (void)out_size;
    const float* ts   = (const float*)d_in[0];
    const float* shp  = (const float*)d_in[1];
    const float* fc_w = (const float*)d_in[2];
    const float* fc_b = (const float*)d_in[3];
    float* out        = (float*)d_out;
    shapelet_kernel<<<Bc, 256>>>(ts, shp, fc_w, fc_b, out);
}

// round 2
// speedup vs baseline: 1.5882x; 1.5882x over previous
#include <cuda_runtime.h>

// ---------------------------------------------------------------------------
// ShapletLearner: B=2048 series (Q=1024), L=64 shapelets (K=32), S=993 windows
//   dist[b,s,l] = (wsq[s] - 2*dot)/K + ssq[l];  d[b,l]=min_s;  out = d@W^T + b
// R2: 8-wide s-blocking per thread (ring-buffer sliding window) to halve
//     shared-memory traffic per FFMA2 -> fma pipe becomes the binding resource.
// ---------------------------------------------------------------------------

constexpr int Bc = 2048;
constexpr int Qc = 1024;
constexpr int Kc = 32;
constexpr int Lc = 64;
constexpr int Sc = Qc - Kc + 1;  // 993

typedef unsigned long long u64;

// d += a*b (packed 2xf32)
#define FFMA2_ACC(d, a, b) \
    asm("fma.rn.f32x2 %0, %1, %2, %0;" : "+l"(d) : "l"(a), "l"(b))
// d = a*b + c (packed 2xf32)
#define FFMA2_3(d, a, b, c) \
    asm("fma.rn.f32x2 %0, %1, %2, %3;" : "=l"(d) : "l"(a), "l"(b), "l"(c))

static __device__ __forceinline__ u64 pack_dup(float x) {
    u64 r;
    asm("mov.b64 %0, {%1, %2};" : "=l"(r) : "f"(x), "f"(x));
    return r;
}
static __device__ __forceinline__ float lo_f(u64 v) {
    return __uint_as_float((unsigned int)v);
}
static __device__ __forceinline__ float hi_f(u64 v) {
    return __uint_as_float((unsigned int)(v >> 32));
}

__global__ __launch_bounds__(256, 2) void shapelet_kernel(
    const float* __restrict__ ts,        // [B, Q]
    const float* __restrict__ shp,       // [L, K]
    const float* __restrict__ fc_w,      // [2, L]
    const float* __restrict__ fc_b,      // [2]
    float* __restrict__ out)             // [B, 2]
{
    __shared__ __align__(16) float ts_sh[Qc + 48];   // reads reach s0+39 (<=1055)
    __shared__ __align__(16) float shp_t[Kc * Lc];   // [k][l]
    __shared__ float ssq_sh[Lc];
    __shared__ float red[Lc * 33];                   // [l][sl], stride 33
    __shared__ float dsh[Lc];

    const int b   = blockIdx.x;
    const int tid = threadIdx.x;

    // ---- stage ts row (float4, coalesced) + zero pad ----
    {
        const float4* src = reinterpret_cast<const float4*>(ts + (size_t)b * Qc);
        reinterpret_cast<float4*>(ts_sh)[tid] = src[tid];
    }
    if (tid < 48) ts_sh[Qc + tid] = 0.0f;

    // ---- transpose shapelets into [k][l] ----
    #pragma unroll
    for (int idx = tid; idx < Lc * Kc; idx += 256) {
        int l = idx >> 5, k = idx & 31;
        shp_t[k * Lc + l] = shp[idx];
    }
    __syncthreads();

    // ---- ssq[l] = mean_k shp^2 ----
    if (tid < Lc) {
        float s = 0.0f;
        #pragma unroll
        for (int k = 0; k < Kc; k++) {
            float v = shp_t[k * Lc + tid];
            s = fmaf(v, v, s);
        }
        ssq_sh[tid] = s * (1.0f / Kc);
    }

    // ---- main: thread -> l in [lg*8, lg*8+8), s in {(it*32+sl)*8 + i, i<8} ----
    const int lg = tid & 7;   // 8 l-groups
    const int sl = tid >> 3;  // 32 s-lanes

    float m[8];
    #pragma unroll
    for (int j = 0; j < 8; j++) m[j] = 3.4e38f;

    const ulonglong2* sp =
        reinterpret_cast<const ulonglong2*>(shp_t) + lg * 2;
    const u64 neg2 = pack_dup(-2.0f);

    #pragma unroll 1
    for (int it = 0; it < 4; it++) {
        const int s0 = (it * 32 + sl) * 8;
        if (s0 >= Sc) continue;

        u64 acc[8][4];
        #pragma unroll
        for (int i = 0; i < 8; i++)
            #pragma unroll
            for (int p = 0; p < 4; p++) acc[i][p] = 0ull;

        // ring buffer: at start of step k, wd[(k+i)&7] = ts[s0+k+i], i=0..7
        u64 wd[8];
        #pragma unroll
        for (int i = 0; i < 8; i++) wd[i] = pack_dup(ts_sh[s0 + i]);

        float wsq0 = 0.0f;

        #pragma unroll
        for (int k = 0; k < Kc; k++) {
            const ulonglong2 sa = sp[k * 16];       // shp pairs l..l+3
            const ulonglong2 sb = sp[k * 16 + 1];   // shp pairs l+4..l+7
            const float w0c = lo_f(wd[k & 7]);
            wsq0 = fmaf(w0c, w0c, wsq0);
            #pragma unroll
            for (int i = 0; i < 8; i++) {
                const u64 w = wd[(k + i) & 7];
                FFMA2_ACC(acc[i][0], sa.x, w);
                FFMA2_ACC(acc[i][1], sa.y, w);
                FFMA2_ACC(acc[i][2], sb.x, w);
                FFMA2_ACC(acc[i][3], sb.y, w);
            }
            // refill slot just consumed as i=0; serves i=7 next step
            wd[k & 7] = pack_dup(ts_sh[s0 + k + 8]);
        }

        // incremental window sum-of-squares for s0+1..s0+7
        float wsq[8];
        wsq[0] = wsq0;
        #pragma unroll
        for (int i = 1; i < 8; i++) {
            const float t = ts_sh[s0 + i - 1];
            const float u = ts_sh[s0 + 32 + i - 1];
            wsq[i] = wsq[i - 1] - t * t + u * u;
        }

        const bool fullv = (s0 + 8 <= Sc);
        #pragma unroll
        for (int i = 0; i < 8; i++) {
            if (fullv || (s0 + i) < Sc) {
                const u64 wq = pack_dup(wsq[i]);
                #pragma unroll
                for (int p = 0; p < 4; p++) {
                    u64 v;
                    FFMA2_3(v, acc[i][p], neg2, wq);   // wsq - 2*dot (packed)
                    m[2 * p]     = fminf(m[2 * p],     lo_f(v));
                    m[2 * p + 1] = fminf(m[2 * p + 1], hi_f(v));
                }
            }
        }
    }

    // ---- cross-s_lane min reduction ----
    #pragma unroll
    for (int j = 0; j < 8; j++)
        red[(lg * 8 + j) * 33 + sl] = m[j];
    __syncthreads();

    if (tid < Lc) {
        float mm = red[tid * 33];
        #pragma unroll
        for (int r = 1; r < 32; r++) mm = fminf(mm, red[tid * 33 + r]);
        dsh[tid] = mm * (1.0f / Kc) + ssq_sh[tid];
    }
    __syncthreads();

    // ---- FC epilogue: warp 0 -> class 0, warp 1 -> class 1 ----
    if (tid < 2 * 32) {
        const int c    = tid >> 5;
        const int lane = tid & 31;
        float p = dsh[lane] * fc_w[c * Lc + lane]
                + dsh[lane + 32] * fc_w[c * Lc + lane + 32];
        #pragma unroll
        for (int off = 16; off > 0; off >>= 1)
            p += __shfl_down_sync(0xffffffffu, p, off);
        if (lane == 0) out[b * 2 + c] = p + fc_b[c];
    }
}

extern "C" void kernel_launch(void* const* d_in, const int* in_sizes, int n_in,
                              void* d_out, int out_size)
{
    (void)in_sizes; (void)n_in; (void)out_size;
    const float* ts   = (const float*)d_in[0];
    const float* shp  = (const float*)d_in[1];
    const float* fc_w = (const float*)d_in[2];
    const float* fc_b = (const float*)d_in[3];
    float* out        = (float*)d_out;
    shapelet_kernel<<<Bc, 256>>>(ts, shp, fc_w, fc_b, out);
}